// round 1
// baseline (speedup 1.0000x reference)
#include <cuda_runtime.h>
#include <cstddef>
#include <cstdint>

#define S_    1024
#define H_    1024
#define HD_   64
#define NH_   16
#define KVH_  8
#define E_    64
#define TOPK_ 8
#define CAP_  512
#define I_    3072
#define QKVN_ 2048

// ---------------- static scratch (no allocations allowed) ----------------
// float buffer layout (element offsets):
static const size_t OFF_X      = 0;          // 1048576  rmsnorm1 out
static const size_t OFF_QKV    = 1048576;    // 2097152
static const size_t OFF_Q      = 3145728;    // 1048576  [NH][S][HD]
static const size_t OFF_K      = 4194304;    // 524288   [KVH][S][HD]
static const size_t OFF_V      = 4718592;    // 524288
static const size_t OFF_ATTN   = 5242880;    // 1048576  [S][NH*HD]
static const size_t OFF_H1     = 6291456;    // 1048576
static const size_t OFF_X2     = 7340032;    // 1048576
static const size_t OFF_ACTSH  = 8388608;    // 3145728  [S][I]
static const size_t OFF_LOGITS = 11534336;   // 65536
static const size_t OFF_W8     = 11599872;   // 8192
static const size_t OFF_EXPW   = 11608064;   // 32768    [E][CAP]
static const size_t OFF_ACTEXP = 11640832;   // 100663296 [E][CAP][I]
static const size_t FBUF_TOT   = 112304128;  // ~449 MB

static const size_t IOFF_IDX8   = 0;         // 8192
static const size_t IOFF_EXPTOK = 8192;      // 32768
static const size_t IOFF_EXPCNT = 40960;     // 64

__device__ float g_fbuf[FBUF_TOT];
__device__ int   g_ibuf[41028];

// ---------------- RMSNorm (row per block) ----------------
__global__ void rmsnorm_kernel(const float* __restrict__ in, const float* __restrict__ w,
                               float* __restrict__ out) {
    int row = blockIdx.x, tid = threadIdx.x;
    const float* x = in + (size_t)row * H_;
    float s = 0.f;
    for (int i = tid; i < H_; i += 256) { float v = x[i]; s += v * v; }
    __shared__ float red[256];
    red[tid] = s; __syncthreads();
    for (int o = 128; o > 0; o >>= 1) { if (tid < o) red[tid] += red[tid + o]; __syncthreads(); }
    float sc = rsqrtf(red[0] * (1.f / H_) + 1e-6f);
    for (int i = tid; i < H_; i += 256) out[(size_t)row * H_ + i] = x[i] * sc * w[i];
}

// ---------------- generic SGEMM: C = A(MxK) @ B(KxN) [+ D], M,N mult of 128, K mult of 16 ----
template<bool ADD>
__global__ void gemm_kernel(const float* __restrict__ A, const float* __restrict__ B,
                            const float* __restrict__ D, float* __restrict__ C,
                            int M, int N, int Kd) {
    __shared__ float As[16][132];
    __shared__ float Bs[16][128];
    int tid = threadIdx.x;
    int ty = tid >> 4, tx = tid & 15;
    int row0 = blockIdx.y * 128, col0 = blockIdx.x * 128;
    float acc[8][8];
#pragma unroll
    for (int i = 0; i < 8; i++)
#pragma unroll
        for (int j = 0; j < 8; j++) acc[i][j] = 0.f;

    for (int kt = 0; kt < Kd; kt += 16) {
#pragma unroll
        for (int s = 0; s < 8; s++) {
            int idx = tid + 256 * s;
            int k = idx & 15, m = idx >> 4;
            As[k][m] = A[(size_t)(row0 + m) * Kd + kt + k];
        }
#pragma unroll
        for (int s = 0; s < 8; s++) {
            int idx = tid + 256 * s;
            int n = idx & 127, k = idx >> 7;
            Bs[k][n] = B[(size_t)(kt + k) * N + col0 + n];
        }
        __syncthreads();
#pragma unroll
        for (int k = 0; k < 16; k++) {
            float a[8], b[8];
#pragma unroll
            for (int i = 0; i < 8; i++) a[i] = As[k][ty * 8 + i];
#pragma unroll
            for (int j = 0; j < 8; j++) b[j] = Bs[k][tx * 8 + j];
#pragma unroll
            for (int i = 0; i < 8; i++)
#pragma unroll
                for (int j = 0; j < 8; j++) acc[i][j] = fmaf(a[i], b[j], acc[i][j]);
        }
        __syncthreads();
    }
#pragma unroll
    for (int i = 0; i < 8; i++) {
        int r = row0 + ty * 8 + i;
#pragma unroll
        for (int j = 0; j < 8; j++) {
            int c = col0 + tx * 8 + j;
            float v = acc[i][j];
            if (ADD) v += D[(size_t)r * N + c];
            C[(size_t)r * N + c] = v;
        }
    }
}

// ---------------- QKV postprocess: RoPE + per-head RMSNorm, head-major layout ----------------
__global__ void qkvproc_kernel(const float* __restrict__ qkv, const float* __restrict__ cosb,
                               const float* __restrict__ sinb, const float* __restrict__ qnw,
                               const float* __restrict__ knw, float* __restrict__ q,
                               float* __restrict__ k, float* __restrict__ v) {
    int s = blockIdx.x, tid = threadIdx.x;
    int w = tid >> 5, lane = tid & 31;
#pragma unroll
    for (int p = 0; p < 4; p++) {
        int r = w + 8 * p;            // 0..31
        int kv = r >> 2, slot = r & 3;
        int base = s * QKVN_ + kv * 256 + slot * 64;
        int d0 = lane * 2, d1 = d0 + 1;
        float x0 = qkv[base + d0], x1 = qkv[base + d1];
        float y0, y1;
        if (slot == 3) { y0 = x0; y1 = x1; }
        else {
            float p0 = __shfl_xor_sync(0xffffffffu, x0, 16);
            float p1 = __shfl_xor_sync(0xffffffffu, x1, 16);
            float rh0 = (lane < 16) ? -p0 : p0;
            float rh1 = (lane < 16) ? -p1 : p1;
            float c0 = cosb[s * HD_ + d0], s0 = sinb[s * HD_ + d0];
            float c1 = cosb[s * HD_ + d1], s1 = sinb[s * HD_ + d1];
            y0 = x0 * c0 + rh0 * s0;
            y1 = x1 * c1 + rh1 * s1;
            float ss = y0 * y0 + y1 * y1;
            for (int off = 16; off > 0; off >>= 1) ss += __shfl_xor_sync(0xffffffffu, ss, off);
            float scn = rsqrtf(ss * (1.f / HD_) + 1e-6f);
            const float* wn = (slot < 2) ? qnw : knw;
            y0 = y0 * scn * wn[d0];
            y1 = y1 * scn * wn[d1];
        }
        if (slot < 2) {
            int hh = kv * 2 + slot;
            size_t off = ((size_t)hh * S_ + s) * HD_;
            q[off + d0] = y0; q[off + d1] = y1;
        } else if (slot == 2) {
            size_t off = ((size_t)kv * S_ + s) * HD_;
            k[off + d0] = y0; k[off + d1] = y1;
        } else {
            size_t off = ((size_t)kv * S_ + s) * HD_;
            v[off + d0] = y0; v[off + d1] = y1;
        }
    }
}

// ---------------- flash attention (BQ=64, BK=32, 256 threads) ----------------
__global__ void attn_kernel(const float* __restrict__ qg, const float* __restrict__ kg,
                            const float* __restrict__ vg, float* __restrict__ attn) {
    int qt = blockIdx.x, h = blockIdx.y;
    int q0 = qt * 64;
    const float* Q = qg + ((size_t)h * S_ + q0) * HD_;
    const float* Kp = kg + ((size_t)(h >> 1) * S_) * HD_;
    const float* Vp = vg + ((size_t)(h >> 1) * S_) * HD_;
    __shared__ float Qs[64][65];
    __shared__ float U[64][33];  // union: KsT[d][key] then Ps[row][key]
    __shared__ float Vs[32][64];
    int tid = threadIdx.x;
    int ty = tid >> 4, tx = tid & 15;
    {
        int d = tid & 63, r0 = (tid >> 6) * 16;
#pragma unroll
        for (int qq = 0; qq < 16; qq++) Qs[r0 + qq][d] = Q[(size_t)(r0 + qq) * HD_ + d];
    }
    float o[4][4]; float m[4], l[4];
#pragma unroll
    for (int i = 0; i < 4; i++) {
        m[i] = -1e30f; l[i] = 0.f;
#pragma unroll
        for (int j = 0; j < 4; j++) o[i][j] = 0.f;
    }
    int nkt = (q0 + 64) / 32;
    for (int kt = 0; kt < nkt; kt++) {
        int k0 = kt * 32;
        {
            int d = tid & 63, kgp = tid >> 6;
#pragma unroll
            for (int qq = 0; qq < 8; qq++) {
                int key = kgp * 8 + qq;
                U[d][key]  = Kp[(size_t)(k0 + key) * HD_ + d];
                Vs[key][d] = Vp[(size_t)(k0 + key) * HD_ + d];
            }
        }
        __syncthreads();
        float sc[4][2];
#pragma unroll
        for (int i = 0; i < 4; i++) { sc[i][0] = 0.f; sc[i][1] = 0.f; }
        for (int d = 0; d < 64; d++) {
            float qv[4], kv[2];
#pragma unroll
            for (int i = 0; i < 4; i++) qv[i] = Qs[ty * 4 + i][d];
#pragma unroll
            for (int j = 0; j < 2; j++) kv[j] = U[d][tx * 2 + j];
#pragma unroll
            for (int i = 0; i < 4; i++)
#pragma unroll
                for (int j = 0; j < 2; j++) sc[i][j] = fmaf(qv[i], kv[j], sc[i][j]);
        }
        __syncthreads();  // done reading KsT
        float pr[4][2];
#pragma unroll
        for (int i = 0; i < 4; i++) {
            int qrow = q0 + ty * 4 + i;
            float mi = -1e30f;
            bool msk[2];
#pragma unroll
            for (int j = 0; j < 2; j++) {
                int kc = k0 + tx * 2 + j;
                msk[j] = (kc > qrow);
                float vv = msk[j] ? -1e30f : sc[i][j] * 0.125f;
                sc[i][j] = vv;
                mi = fmaxf(mi, vv);
            }
            for (int off = 8; off > 0; off >>= 1) mi = fmaxf(mi, __shfl_xor_sync(0xffffffffu, mi, off));
            float mn = fmaxf(m[i], mi);
            float corr = __expf(m[i] - mn);
            float rs = 0.f;
#pragma unroll
            for (int j = 0; j < 2; j++) {
                pr[i][j] = msk[j] ? 0.f : __expf(sc[i][j] - mn);
                rs += pr[i][j];
            }
            for (int off = 8; off > 0; off >>= 1) rs += __shfl_xor_sync(0xffffffffu, rs, off);
            l[i] = l[i] * corr + rs;
            m[i] = mn;
#pragma unroll
            for (int jj = 0; jj < 4; jj++) o[i][jj] *= corr;
        }
#pragma unroll
        for (int i = 0; i < 4; i++)
#pragma unroll
            for (int j = 0; j < 2; j++) U[ty * 4 + i][tx * 2 + j] = pr[i][j];
        __syncthreads();
        for (int k = 0; k < 32; k++) {
            float pv[4], vv[4];
#pragma unroll
            for (int i = 0; i < 4; i++) pv[i] = U[ty * 4 + i][k];
#pragma unroll
            for (int jj = 0; jj < 4; jj++) vv[jj] = Vs[k][tx * 4 + jj];
#pragma unroll
            for (int i = 0; i < 4; i++)
#pragma unroll
                for (int jj = 0; jj < 4; jj++) o[i][jj] = fmaf(pv[i], vv[jj], o[i][jj]);
        }
        __syncthreads();
    }
#pragma unroll
    for (int i = 0; i < 4; i++) {
        float inv = 1.f / l[i];
#pragma unroll
        for (int jj = 0; jj < 4; jj++)
            attn[(size_t)(q0 + ty * 4 + i) * H_ + h * HD_ + tx * 4 + jj] = o[i][jj] * inv;
    }
}

// ---------------- gate logits + softmax + top-8 (block per token, 64 threads) ----------------
__global__ void gate_topk_kernel(const float* __restrict__ x2, const float* __restrict__ Wg,
                                 float* __restrict__ w8, int* __restrict__ idx8) {
    int t = blockIdx.x, tid = threadIdx.x;
    const float* xr = x2 + (size_t)t * H_;
    float a0 = 0.f, a1 = 0.f, a2 = 0.f, a3 = 0.f;
    for (int h = 0; h < H_; h += 4) {
        a0 = fmaf(xr[h],     Wg[(size_t)h * E_ + tid],       a0);
        a1 = fmaf(xr[h + 1], Wg[(size_t)(h + 1) * E_ + tid], a1);
        a2 = fmaf(xr[h + 2], Wg[(size_t)(h + 2) * E_ + tid], a2);
        a3 = fmaf(xr[h + 3], Wg[(size_t)(h + 3) * E_ + tid], a3);
    }
    float logit = (a0 + a1) + (a2 + a3);
    __shared__ float red[64];
    __shared__ float gv[64];
    red[tid] = logit; __syncthreads();
    for (int o = 32; o > 0; o >>= 1) { if (tid < o) red[tid] = fmaxf(red[tid], red[tid + o]); __syncthreads(); }
    float mx = red[0]; __syncthreads();
    float ex = __expf(logit - mx);
    red[tid] = ex; __syncthreads();
    for (int o = 32; o > 0; o >>= 1) { if (tid < o) red[tid] += red[tid + o]; __syncthreads(); }
    float sum = red[0];
    gv[tid] = ex / sum; __syncthreads();
    if (tid == 0) {
        bool used[E_];
        for (int e = 0; e < E_; e++) used[e] = false;
        float wv[TOPK_]; int id[TOPK_]; float wsum = 0.f;
        for (int r = 0; r < TOPK_; r++) {
            int best = 0; float bv = -1e30f;
            for (int e = 0; e < E_; e++)
                if (!used[e] && gv[e] > bv) { bv = gv[e]; best = e; }
            used[best] = true; wv[r] = bv; id[r] = best; wsum += bv;
        }
        wsum = fmaxf(wsum, 1.1920929e-07f);
        for (int r = 0; r < TOPK_; r++) {
            w8[t * TOPK_ + r] = wv[r] / wsum;
            idx8[t * TOPK_ + r] = id[r];
        }
    }
}

// ---------------- routing: per-expert slot table, flat-order positions, capacity ----------------
__global__ void route_kernel(const int* __restrict__ idx8, const float* __restrict__ w8,
                             int* __restrict__ etok, float* __restrict__ ew, int* __restrict__ ecnt) {
    int e = blockIdx.x, lane = threadIdx.x;
    int cnt = 0;
    for (int base = 0; base < S_ * TOPK_; base += 32) {
        int j = base + lane;
        int ee = idx8[j];
        bool match = (ee == e);
        unsigned bal = __ballot_sync(0xffffffffu, match);
        int pre = __popc(bal & ((1u << lane) - 1u));
        if (match) {
            int p = cnt + pre;
            if (p < CAP_) {
                etok[e * CAP_ + p] = j >> 3;
                ew[e * CAP_ + p] = w8[j];
            }
        }
        cnt += __popc(bal);
    }
    if (lane == 0) ecnt[e] = (cnt < CAP_) ? cnt : CAP_;
}

// ---------------- fused SwiGLU GEMM (dual-N): act = (A@B[:, :I]) * silu(A@B[:, I:]) --------
template<bool EXPERT>
__global__ void swiglu_kernel(const float* __restrict__ Abase, const float* __restrict__ Wgu,
                              const int* __restrict__ etok, const int* __restrict__ ecnt,
                              float* __restrict__ actout) {
    int e = blockIdx.z;
    int cnt = EXPERT ? ecnt[e] : S_;
    int row0 = blockIdx.y * 128;
    if (row0 >= cnt) return;
    const float* B = EXPERT ? (Wgu + (size_t)e * H_ * 2 * I_) : Wgu;
    float* out = EXPERT ? (actout + (size_t)e * CAP_ * I_) : actout;
    int col0 = blockIdx.x * 64;
    __shared__ float As[16][132];
    __shared__ float Ba[16][64];
    __shared__ float Bb[16][64];
    __shared__ int toks[128];
    int tid = threadIdx.x;
    if (tid < 128)
        toks[tid] = EXPERT ? ((row0 + tid < cnt) ? etok[e * CAP_ + row0 + tid] : 0) : (row0 + tid);
    __syncthreads();
    int ty = tid >> 4, tx = tid & 15;
    float ca[8][4], cb[8][4];
#pragma unroll
    for (int i = 0; i < 8; i++)
#pragma unroll
        for (int j = 0; j < 4; j++) { ca[i][j] = 0.f; cb[i][j] = 0.f; }
    const int ldb = 2 * I_;
    for (int kt = 0; kt < H_; kt += 16) {
#pragma unroll
        for (int s = 0; s < 8; s++) {
            int idx = tid + 256 * s;
            int k = idx & 15, mm = idx >> 4;
            As[k][mm] = Abase[(size_t)toks[mm] * H_ + kt + k];
        }
#pragma unroll
        for (int s = 0; s < 4; s++) {
            int idx = tid + 256 * s;
            int n = idx & 63, k = idx >> 6;
            Ba[k][n] = B[(size_t)(kt + k) * ldb + col0 + n];
            Bb[k][n] = B[(size_t)(kt + k) * ldb + col0 + I_ + n];
        }
        __syncthreads();
#pragma unroll
        for (int k = 0; k < 16; k++) {
            float a[8], ba[4], bb[4];
#pragma unroll
            for (int i = 0; i < 8; i++) a[i] = As[k][ty * 8 + i];
#pragma unroll
            for (int j = 0; j < 4; j++) { ba[j] = Ba[k][tx * 4 + j]; bb[j] = Bb[k][tx * 4 + j]; }
#pragma unroll
            for (int i = 0; i < 8; i++)
#pragma unroll
                for (int j = 0; j < 4; j++) {
                    ca[i][j] = fmaf(a[i], ba[j], ca[i][j]);
                    cb[i][j] = fmaf(a[i], bb[j], cb[i][j]);
                }
        }
        __syncthreads();
    }
#pragma unroll
    for (int i = 0; i < 8; i++) {
        int r = row0 + ty * 8 + i;
        if (r < cnt) {
#pragma unroll
            for (int j = 0; j < 4; j++) {
                int c = col0 + tx * 4 + j;
                float xa = ca[i][j], xb = cb[i][j];
                float sig = 1.f / (1.f + __expf(-xb));
                out[(size_t)r * I_ + c] = xa * xb * sig;
            }
        }
    }
}

// ---------------- expert down-proj + weighted scatter (atomicAdd into out) ----------------
__global__ void moe_gemm2_kernel(const float* __restrict__ actexp, const float* __restrict__ Wd,
                                 const int* __restrict__ etok, const float* __restrict__ ew,
                                 const int* __restrict__ ecnt, float* __restrict__ out) {
    int e = blockIdx.z;
    int cnt = ecnt[e];
    int row0 = blockIdx.y * 128;
    if (row0 >= cnt) return;
    int col0 = blockIdx.x * 128;
    const float* A = actexp + (size_t)e * CAP_ * I_;
    const float* B = Wd + (size_t)e * I_ * H_;
    __shared__ float As[16][132];
    __shared__ float Bs[16][128];
    __shared__ int toks[128];
    __shared__ float ws[128];
    int tid = threadIdx.x;
    if (tid < 128) {
        int r = row0 + tid;
        bool v = r < cnt;
        toks[tid] = v ? etok[e * CAP_ + r] : 0;
        ws[tid] = v ? ew[e * CAP_ + r] : 0.f;
    }
    __syncthreads();
    int ty = tid >> 4, tx = tid & 15;
    float acc[8][8];
#pragma unroll
    for (int i = 0; i < 8; i++)
#pragma unroll
        for (int j = 0; j < 8; j++) acc[i][j] = 0.f;
    for (int kt = 0; kt < I_; kt += 16) {
#pragma unroll
        for (int s = 0; s < 8; s++) {
            int idx = tid + 256 * s;
            int k = idx & 15, mm = idx >> 4;
            As[k][mm] = A[(size_t)(row0 + mm) * I_ + kt + k];
        }
#pragma unroll
        for (int s = 0; s < 8; s++) {
            int idx = tid + 256 * s;
            int n = idx & 127, k = idx >> 7;
            Bs[k][n] = B[(size_t)(kt + k) * H_ + col0 + n];
        }
        __syncthreads();
#pragma unroll
        for (int k = 0; k < 16; k++) {
            float a[8], b[8];
#pragma unroll
            for (int i = 0; i < 8; i++) a[i] = As[k][ty * 8 + i];
#pragma unroll
            for (int j = 0; j < 8; j++) b[j] = Bs[k][tx * 8 + j];
#pragma unroll
            for (int i = 0; i < 8; i++)
#pragma unroll
                for (int j = 0; j < 8; j++) acc[i][j] = fmaf(a[i], b[j], acc[i][j]);
        }
        __syncthreads();
    }
#pragma unroll
    for (int i = 0; i < 8; i++) {
        int rl = ty * 8 + i;
        if (row0 + rl < cnt) {
            int tok = toks[rl];
            float wv = ws[rl];
#pragma unroll
            for (int j = 0; j < 8; j++)
                atomicAdd(&out[(size_t)tok * H_ + col0 + tx * 8 + j], acc[i][j] * wv);
        }
    }
}

// ---------------- launch ----------------
extern "C" void kernel_launch(void* const* d_in, const int* in_sizes, int n_in,
                              void* d_out, int out_size) {
    (void)in_sizes; (void)n_in; (void)out_size;
    const float* hidden = (const float*)d_in[0];
    const float* cosb   = (const float*)d_in[1];
    const float* sinb   = (const float*)d_in[2];
    const float* ln1    = (const float*)d_in[3];
    const float* ln2    = (const float*)d_in[4];
    const float* Wqkv   = (const float*)d_in[5];
    const float* Wo     = (const float*)d_in[6];
    const float* qnw    = (const float*)d_in[7];
    const float* knw    = (const float*)d_in[8];
    const float* Wgu_sh = (const float*)d_in[9];
    const float* Wd_sh  = (const float*)d_in[10];
    const float* Wgate  = (const float*)d_in[11];
    const float* Wgu_e  = (const float*)d_in[12];
    const float* Wd_e   = (const float*)d_in[13];
    float* out = (float*)d_out;

    float* fb = nullptr; int* ib = nullptr;
    cudaGetSymbolAddress((void**)&fb, g_fbuf);
    cudaGetSymbolAddress((void**)&ib, g_ibuf);

    float* x      = fb + OFF_X;
    float* qkv    = fb + OFF_QKV;
    float* q      = fb + OFF_Q;
    float* k      = fb + OFF_K;
    float* v      = fb + OFF_V;
    float* attn   = fb + OFF_ATTN;
    float* h1     = fb + OFF_H1;
    float* x2     = fb + OFF_X2;
    float* actsh  = fb + OFF_ACTSH;
    float* w8     = fb + OFF_W8;
    float* expw   = fb + OFF_EXPW;
    float* actexp = fb + OFF_ACTEXP;
    int* idx8   = ib + IOFF_IDX8;
    int* exptok = ib + IOFF_EXPTOK;
    int* expcnt = ib + IOFF_EXPCNT;

    // 1. x = rmsnorm(hidden, ln1)
    rmsnorm_kernel<<<S_, 256>>>(hidden, ln1, x);
    // 2. qkv = x @ Wqkv
    gemm_kernel<false><<<dim3(QKVN_ / 128, S_ / 128), 256>>>(x, Wqkv, nullptr, qkv, S_, QKVN_, H_);
    // 3. RoPE + QK-norm + layout
    qkvproc_kernel<<<S_, 256>>>(qkv, cosb, sinb, qnw, knw, q, k, v);
    // 4. causal GQA attention
    attn_kernel<<<dim3(S_ / 64, NH_), 256>>>(q, k, v, attn);
    // 5. h1 = attn @ Wo + hidden
    gemm_kernel<true><<<dim3(H_ / 128, S_ / 128), 256>>>(attn, Wo, hidden, h1, S_, H_, H_);
    // 6. x2 = rmsnorm(h1, ln2)
    rmsnorm_kernel<<<S_, 256>>>(h1, ln2, x2);
    // 7. shared MLP swiglu activation
    swiglu_kernel<false><<<dim3(I_ / 64, S_ / 128, 1), 256>>>(x2, Wgu_sh, nullptr, nullptr, actsh);
    // 8. out = actsh @ Wd_sh + h1
    gemm_kernel<true><<<dim3(H_ / 128, S_ / 128), 256>>>(actsh, Wd_sh, h1, out, S_, H_, I_);
    // 9. gate logits + softmax + top-8
    gate_topk_kernel<<<S_, 64>>>(x2, Wgate, w8, idx8);
    // 10. routing with capacity
    route_kernel<<<E_, 32>>>(idx8, w8, exptok, expw, expcnt);
    // 11. expert swiglu (gathered rows)
    swiglu_kernel<true><<<dim3(I_ / 64, CAP_ / 128, E_), 256>>>(x2, Wgu_e, exptok, expcnt, actexp);
    // 12. expert down-proj + weighted scatter into out
    moe_gemm2_kernel<<<dim3(H_ / 128, CAP_ / 128, E_), 256>>>(actexp, Wd_e, exptok, expw, expcnt, out);
}

// round 3
// speedup vs baseline: 3.4829x; 3.4829x over previous
#include <cuda_runtime.h>
#include <cstddef>
#include <cstdint>

#define S_    1024
#define H_    1024
#define HD_   64
#define NH_   16
#define KVH_  8
#define E_    64
#define TOPK_ 8
#define CAP_  512
#define I_    3072
#define QKVN_ 2048

// ---------------- static scratch ----------------
static const size_t OFF_X      = 0;
static const size_t OFF_QKV    = 1048576;
static const size_t OFF_Q      = 3145728;
static const size_t OFF_K      = 4194304;
static const size_t OFF_V      = 4718592;
static const size_t OFF_ATTN   = 5242880;
static const size_t OFF_H1     = 6291456;
static const size_t OFF_X2     = 7340032;
static const size_t OFF_ACTSH  = 8388608;
static const size_t OFF_W8     = 11599872;
static const size_t OFF_EXPW   = 11608064;
static const size_t OFF_ACTEXP = 11640832;
static const size_t FBUF_TOT   = 112304128;

static const size_t IOFF_IDX8   = 0;
static const size_t IOFF_EXPTOK = 8192;
static const size_t IOFF_EXPCNT = 40960;

__device__ float g_fbuf[FBUF_TOT];
__device__ int   g_ibuf[41028];

__device__ __forceinline__ uint32_t f2tf32(float f) {
    uint32_t r; asm("cvt.rna.tf32.f32 %0, %1;" : "=r"(r) : "f"(f)); return r;
}

__device__ __forceinline__ void mma_tf32(float* c, const uint32_t* a, const uint32_t* b) {
    asm volatile(
        "mma.sync.aligned.m16n8k8.row.col.f32.tf32.tf32.f32 "
        "{%0,%1,%2,%3}, {%4,%5,%6,%7}, {%8,%9}, {%0,%1,%2,%3};"
        : "+f"(c[0]), "+f"(c[1]), "+f"(c[2]), "+f"(c[3])
        : "r"(a[0]), "r"(a[1]), "r"(a[2]), "r"(a[3]), "r"(b[0]), "r"(b[1]));
}

// ---------------- tf32 mma.sync GEMM ----------------
// Block tile 128x128, K-chunk 16, 8 warps (2 m x 4 n), warp tile 64x32.
// MODE 0: plain  1: plain+add  2: shared swiglu  3: expert swiglu (gather rows)
// MODE 4: expert down-proj + weighted atomic scatter
#define A_STRIDE 20
#define B_STRIDE 136

template<int MODE>
__global__ void __launch_bounds__(256, 2) mma_gemm(
    const float* __restrict__ A, int lda,
    const float* __restrict__ B, int ldb,
    const float* __restrict__ Dadd,
    float* __restrict__ out, int ldc, int Kdim,
    const int* __restrict__ etok, const float* __restrict__ ew,
    const int* __restrict__ ecnt) {
    constexpr bool IS_SWI = (MODE == 2 || MODE == 3);
    constexpr bool IS_EXP = (MODE == 3 || MODE == 4);

    int e = IS_EXP ? blockIdx.z : 0;
    int cnt = IS_EXP ? ecnt[e] : S_;
    int row0 = blockIdx.y * 128;
    if (IS_EXP && row0 >= cnt) return;
    int bx = blockIdx.x;

    __shared__ float As[2][128][A_STRIDE];
    __shared__ float Bs[2][16][B_STRIDE];
    __shared__ int   toks_s[128];
    __shared__ float ws_s[128];

    int tid = threadIdx.x;
    int wid = tid >> 5;
    int lane = tid & 31;
    int g = lane >> 2, t = lane & 3;
    int wm = wid & 1, wn = wid >> 1;

    const float* Ab = A;
    const float* Bb = B;
    float* outp = out;
    if (MODE == 3) { Bb = B + (size_t)e * H_ * 2 * I_; outp = out + (size_t)e * CAP_ * I_; }
    if (MODE == 4) { Ab = A + (size_t)e * CAP_ * I_; Bb = B + (size_t)e * I_ * H_; }

    if (IS_EXP && tid < 128) {
        int rr = row0 + tid;
        bool v = rr < cnt;
        toks_s[tid] = v ? etok[e * CAP_ + rr] : 0;
        ws_s[tid]   = v ? ew[e * CAP_ + rr] : 0.f;
    }
    if (IS_EXP) __syncthreads();

    // per-thread global load coords
    // A: 512 float4 per chunk: f4 = tid + 256*s, r = f4>>2, q = f4&3
    // B: 512 float4 per chunk: f4 = tid + 256*s, k = f4>>5, nq = f4&31
    const float* arow_ptr[2];
    int aq[2];
#pragma unroll
    for (int s = 0; s < 2; s++) {
        int f4 = tid + 256 * s;
        int r = f4 >> 2; aq[s] = (f4 & 3) * 4;
        if (MODE == 3) arow_ptr[s] = A + (size_t)toks_s[r] * lda;
        else           arow_ptr[s] = Ab + (size_t)(row0 + r) * lda;
    }
    const float* brow_base[2];
    int bk_[2];
#pragma unroll
    for (int s = 0; s < 2; s++) {
        int f4 = tid + 256 * s;
        int k = f4 >> 5, nq = f4 & 31;
        int col;
        if (IS_SWI) col = (nq < 16) ? (bx * 64 + nq * 4) : (I_ + bx * 64 + (nq - 16) * 4);
        else        col = bx * 128 + nq * 4;
        bk_[s] = k;
        brow_base[s] = Bb + (size_t)k * ldb + col;
    }

    float4 aR[2], bR[2];
    auto ldg = [&](int kt) {
#pragma unroll
        for (int s = 0; s < 2; s++) {
            aR[s] = *(const float4*)(arow_ptr[s] + kt + aq[s]);
            bR[s] = *(const float4*)(brow_base[s] + (size_t)kt * ldb);
        }
    };
    auto sts = [&](int buf) {
#pragma unroll
        for (int s = 0; s < 2; s++) {
            int f4 = tid + 256 * s;
            int r = f4 >> 2, q = (f4 & 3) * 4;
            float* d = &As[buf][r][q];
            d[0] = __uint_as_float(f2tf32(aR[s].x));
            d[1] = __uint_as_float(f2tf32(aR[s].y));
            d[2] = __uint_as_float(f2tf32(aR[s].z));
            d[3] = __uint_as_float(f2tf32(aR[s].w));
            int nq = f4 & 31;
            float* d2 = &Bs[buf][bk_[s]][nq * 4];
            d2[0] = __uint_as_float(f2tf32(bR[s].x));
            d2[1] = __uint_as_float(f2tf32(bR[s].y));
            d2[2] = __uint_as_float(f2tf32(bR[s].z));
            d2[3] = __uint_as_float(f2tf32(bR[s].w));
        }
    };

    float acc[4][4][4];
#pragma unroll
    for (int mi = 0; mi < 4; mi++)
#pragma unroll
        for (int ni = 0; ni < 4; ni++)
#pragma unroll
            for (int p = 0; p < 4; p++) acc[mi][ni][p] = 0.f;

    ldg(0); sts(0);
    __syncthreads();

    int NC = Kdim / 16;
    for (int c = 0; c < NC; c++) {
        int cur = c & 1;
        if (c + 1 < NC) ldg((c + 1) * 16);
#pragma unroll
        for (int k0 = 0; k0 < 16; k0 += 8) {
            uint32_t af[4][4], bf[4][2];
#pragma unroll
            for (int mi = 0; mi < 4; mi++) {
                int m0 = wm * 64 + mi * 16;
                af[mi][0] = __float_as_uint(As[cur][m0 + g][k0 + t]);
                af[mi][1] = __float_as_uint(As[cur][m0 + g + 8][k0 + t]);
                af[mi][2] = __float_as_uint(As[cur][m0 + g][k0 + t + 4]);
                af[mi][3] = __float_as_uint(As[cur][m0 + g + 8][k0 + t + 4]);
            }
#pragma unroll
            for (int ni = 0; ni < 4; ni++) {
                int n0;
                if (IS_SWI) n0 = (ni < 2) ? (wn * 16 + ni * 8) : (64 + wn * 16 + (ni - 2) * 8);
                else        n0 = wn * 32 + ni * 8;
                bf[ni][0] = __float_as_uint(Bs[cur][k0 + t][n0 + g]);
                bf[ni][1] = __float_as_uint(Bs[cur][k0 + t + 4][n0 + g]);
            }
#pragma unroll
            for (int mi = 0; mi < 4; mi++)
#pragma unroll
                for (int ni = 0; ni < 4; ni++)
                    mma_tf32(acc[mi][ni], af[mi], bf[ni]);
        }
        if (c + 1 < NC) sts(cur ^ 1);
        __syncthreads();
    }

    // ---------------- epilogue ----------------
    if (MODE == 0 || MODE == 1) {
#pragma unroll
        for (int mi = 0; mi < 4; mi++) {
            int r = row0 + wm * 64 + mi * 16 + g;
#pragma unroll
            for (int ni = 0; ni < 4; ni++) {
                int col = bx * 128 + wn * 32 + ni * 8 + 2 * t;
                float2 v0 = make_float2(acc[mi][ni][0], acc[mi][ni][1]);
                float2 v1 = make_float2(acc[mi][ni][2], acc[mi][ni][3]);
                if (MODE == 1) {
                    float2 d0 = *(const float2*)(Dadd + (size_t)r * ldc + col);
                    float2 d1 = *(const float2*)(Dadd + (size_t)(r + 8) * ldc + col);
                    v0.x += d0.x; v0.y += d0.y; v1.x += d1.x; v1.y += d1.y;
                }
                *(float2*)(outp + (size_t)r * ldc + col) = v0;
                *(float2*)(outp + (size_t)(r + 8) * ldc + col) = v1;
            }
        }
    } else if (IS_SWI) {
#pragma unroll
        for (int mi = 0; mi < 4; mi++) {
            int rl = wm * 64 + mi * 16 + g;
            int r = row0 + rl;
#pragma unroll
            for (int ni = 0; ni < 2; ni++) {
                int col = bx * 64 + wn * 16 + ni * 8 + 2 * t;
#pragma unroll
                for (int h = 0; h < 2; h++) {   // h=0: row r, h=1: row r+8
                    int rr = (MODE == 3) ? (rl + 8 * h) : 0;
                    int rg = r + 8 * h;
                    if (MODE == 3 && rg >= cnt) continue;
                    float gg0 = acc[mi][ni][2 * h + 0], gg1 = acc[mi][ni][2 * h + 1];
                    float uu0 = acc[mi][ni + 2][2 * h + 0], uu1 = acc[mi][ni + 2][2 * h + 1];
                    float s0 = 1.f / (1.f + __expf(-uu0));
                    float s1 = 1.f / (1.f + __expf(-uu1));
                    float2 v = make_float2(gg0 * uu0 * s0, gg1 * uu1 * s1);
                    size_t orow = (MODE == 3) ? (size_t)(row0 + rr) : (size_t)rg;
                    *(float2*)(outp + orow * I_ + col) = v;
                }
            }
        }
    } else {  // MODE 4
#pragma unroll
        for (int mi = 0; mi < 4; mi++) {
            int rl = wm * 64 + mi * 16 + g;
#pragma unroll
            for (int h = 0; h < 2; h++) {
                int rr = rl + 8 * h;
                if (row0 + rr >= cnt) continue;
                int tok = toks_s[rr];
                float wv = ws_s[rr];
#pragma unroll
                for (int ni = 0; ni < 4; ni++) {
                    int col = bx * 128 + wn * 32 + ni * 8 + 2 * t;
                    atomicAdd(out + (size_t)tok * H_ + col,     acc[mi][ni][2 * h + 0] * wv);
                    atomicAdd(out + (size_t)tok * H_ + col + 1, acc[mi][ni][2 * h + 1] * wv);
                }
            }
        }
    }
}

// ---------------- RMSNorm ----------------
__global__ void rmsnorm_kernel(const float* __restrict__ in, const float* __restrict__ w,
                               float* __restrict__ out) {
    int row = blockIdx.x, tid = threadIdx.x;
    const float* x = in + (size_t)row * H_;
    float s = 0.f;
    for (int i = tid; i < H_; i += 256) { float v = x[i]; s += v * v; }
    __shared__ float red[256];
    red[tid] = s; __syncthreads();
    for (int o = 128; o > 0; o >>= 1) { if (tid < o) red[tid] += red[tid + o]; __syncthreads(); }
    float sc = rsqrtf(red[0] * (1.f / H_) + 1e-6f);
    for (int i = tid; i < H_; i += 256) out[(size_t)row * H_ + i] = x[i] * sc * w[i];
}

// ---------------- QKV postprocess ----------------
__global__ void qkvproc_kernel(const float* __restrict__ qkv, const float* __restrict__ cosb,
                               const float* __restrict__ sinb, const float* __restrict__ qnw,
                               const float* __restrict__ knw, float* __restrict__ q,
                               float* __restrict__ k, float* __restrict__ v) {
    int s = blockIdx.x, tid = threadIdx.x;
    int w = tid >> 5, lane = tid & 31;
#pragma unroll
    for (int p = 0; p < 4; p++) {
        int r = w + 8 * p;
        int kv = r >> 2, slot = r & 3;
        int base = s * QKVN_ + kv * 256 + slot * 64;
        int d0 = lane * 2, d1 = d0 + 1;
        float x0 = qkv[base + d0], x1 = qkv[base + d1];
        float y0, y1;
        if (slot == 3) { y0 = x0; y1 = x1; }
        else {
            float p0 = __shfl_xor_sync(0xffffffffu, x0, 16);
            float p1 = __shfl_xor_sync(0xffffffffu, x1, 16);
            float rh0 = (lane < 16) ? -p0 : p0;
            float rh1 = (lane < 16) ? -p1 : p1;
            float c0 = cosb[s * HD_ + d0], s0 = sinb[s * HD_ + d0];
            float c1 = cosb[s * HD_ + d1], s1 = sinb[s * HD_ + d1];
            y0 = x0 * c0 + rh0 * s0;
            y1 = x1 * c1 + rh1 * s1;
            float ss = y0 * y0 + y1 * y1;
            for (int off = 16; off > 0; off >>= 1) ss += __shfl_xor_sync(0xffffffffu, ss, off);
            float scn = rsqrtf(ss * (1.f / HD_) + 1e-6f);
            const float* wn = (slot < 2) ? qnw : knw;
            y0 = y0 * scn * wn[d0];
            y1 = y1 * scn * wn[d1];
        }
        if (slot < 2) {
            int hh = kv * 2 + slot;
            size_t off = ((size_t)hh * S_ + s) * HD_;
            q[off + d0] = y0; q[off + d1] = y1;
        } else if (slot == 2) {
            size_t off = ((size_t)kv * S_ + s) * HD_;
            k[off + d0] = y0; k[off + d1] = y1;
        } else {
            size_t off = ((size_t)kv * S_ + s) * HD_;
            v[off + d0] = y0; v[off + d1] = y1;
        }
    }
}

// ---------------- flash attention ----------------
__global__ void attn_kernel(const float* __restrict__ qg, const float* __restrict__ kg,
                            const float* __restrict__ vg, float* __restrict__ attn) {
    int qt = blockIdx.x, h = blockIdx.y;
    int q0 = qt * 64;
    const float* Q = qg + ((size_t)h * S_ + q0) * HD_;
    const float* Kp = kg + ((size_t)(h >> 1) * S_) * HD_;
    const float* Vp = vg + ((size_t)(h >> 1) * S_) * HD_;
    __shared__ float Qs[64][65];
    __shared__ float U[64][33];
    __shared__ float Vs[32][64];
    int tid = threadIdx.x;
    int ty = tid >> 4, tx = tid & 15;
    {
        int d = tid & 63, r0 = (tid >> 6) * 16;
#pragma unroll
        for (int qq = 0; qq < 16; qq++) Qs[r0 + qq][d] = Q[(size_t)(r0 + qq) * HD_ + d];
    }
    float o[4][4]; float m[4], l[4];
#pragma unroll
    for (int i = 0; i < 4; i++) {
        m[i] = -1e30f; l[i] = 0.f;
#pragma unroll
        for (int j = 0; j < 4; j++) o[i][j] = 0.f;
    }
    int nkt = (q0 + 64) / 32;
    for (int kt = 0; kt < nkt; kt++) {
        int k0 = kt * 32;
        {
            int d = tid & 63, kgp = tid >> 6;
#pragma unroll
            for (int qq = 0; qq < 8; qq++) {
                int key = kgp * 8 + qq;
                U[d][key]  = Kp[(size_t)(k0 + key) * HD_ + d];
                Vs[key][d] = Vp[(size_t)(k0 + key) * HD_ + d];
            }
        }
        __syncthreads();
        float sc[4][2];
#pragma unroll
        for (int i = 0; i < 4; i++) { sc[i][0] = 0.f; sc[i][1] = 0.f; }
        for (int d = 0; d < 64; d++) {
            float qv[4], kv[2];
#pragma unroll
            for (int i = 0; i < 4; i++) qv[i] = Qs[ty * 4 + i][d];
#pragma unroll
            for (int j = 0; j < 2; j++) kv[j] = U[d][tx * 2 + j];
#pragma unroll
            for (int i = 0; i < 4; i++)
#pragma unroll
                for (int j = 0; j < 2; j++) sc[i][j] = fmaf(qv[i], kv[j], sc[i][j]);
        }
        __syncthreads();
        float pr[4][2];
#pragma unroll
        for (int i = 0; i < 4; i++) {
            int qrow = q0 + ty * 4 + i;
            float mi = -1e30f;
            bool msk[2];
#pragma unroll
            for (int j = 0; j < 2; j++) {
                int kc = k0 + tx * 2 + j;
                msk[j] = (kc > qrow);
                float vv = msk[j] ? -1e30f : sc[i][j] * 0.125f;
                sc[i][j] = vv;
                mi = fmaxf(mi, vv);
            }
            for (int off = 8; off > 0; off >>= 1) mi = fmaxf(mi, __shfl_xor_sync(0xffffffffu, mi, off));
            float mn = fmaxf(m[i], mi);
            float corr = __expf(m[i] - mn);
            float rs = 0.f;
#pragma unroll
            for (int j = 0; j < 2; j++) {
                pr[i][j] = msk[j] ? 0.f : __expf(sc[i][j] - mn);
                rs += pr[i][j];
            }
            for (int off = 8; off > 0; off >>= 1) rs += __shfl_xor_sync(0xffffffffu, rs, off);
            l[i] = l[i] * corr + rs;
            m[i] = mn;
#pragma unroll
            for (int jj = 0; jj < 4; jj++) o[i][jj] *= corr;
        }
#pragma unroll
        for (int i = 0; i < 4; i++)
#pragma unroll
            for (int j = 0; j < 2; j++) U[ty * 4 + i][tx * 2 + j] = pr[i][j];
        __syncthreads();
        for (int k = 0; k < 32; k++) {
            float pv[4], vv[4];
#pragma unroll
            for (int i = 0; i < 4; i++) pv[i] = U[ty * 4 + i][k];
#pragma unroll
            for (int jj = 0; jj < 4; jj++) vv[jj] = Vs[k][tx * 4 + jj];
#pragma unroll
            for (int i = 0; i < 4; i++)
#pragma unroll
                for (int jj = 0; jj < 4; jj++) o[i][jj] = fmaf(pv[i], vv[jj], o[i][jj]);
        }
        __syncthreads();
    }
#pragma unroll
    for (int i = 0; i < 4; i++) {
        float inv = 1.f / l[i];
#pragma unroll
        for (int jj = 0; jj < 4; jj++)
            attn[(size_t)(q0 + ty * 4 + i) * H_ + h * HD_ + tx * 4 + jj] = o[i][jj] * inv;
    }
}

// ---------------- gate + top-8 ----------------
__global__ void gate_topk_kernel(const float* __restrict__ x2, const float* __restrict__ Wg,
                                 float* __restrict__ w8, int* __restrict__ idx8) {
    int tt = blockIdx.x, tid = threadIdx.x;
    const float* xr = x2 + (size_t)tt * H_;
    float a0 = 0.f, a1 = 0.f, a2 = 0.f, a3 = 0.f;
    for (int h = 0; h < H_; h += 4) {
        a0 = fmaf(xr[h],     Wg[(size_t)h * E_ + tid],       a0);
        a1 = fmaf(xr[h + 1], Wg[(size_t)(h + 1) * E_ + tid], a1);
        a2 = fmaf(xr[h + 2], Wg[(size_t)(h + 2) * E_ + tid], a2);
        a3 = fmaf(xr[h + 3], Wg[(size_t)(h + 3) * E_ + tid], a3);
    }
    float logit = (a0 + a1) + (a2 + a3);
    __shared__ float red[64];
    __shared__ float gv[64];
    red[tid] = logit; __syncthreads();
    for (int o = 32; o > 0; o >>= 1) { if (tid < o) red[tid] = fmaxf(red[tid], red[tid + o]); __syncthreads(); }
    float mx = red[0]; __syncthreads();
    float ex = __expf(logit - mx);
    red[tid] = ex; __syncthreads();
    for (int o = 32; o > 0; o >>= 1) { if (tid < o) red[tid] += red[tid + o]; __syncthreads(); }
    float sum = red[0];
    gv[tid] = ex / sum; __syncthreads();
    if (tid == 0) {
        bool used[E_];
        for (int e = 0; e < E_; e++) used[e] = false;
        float wv[TOPK_]; int id[TOPK_]; float wsum = 0.f;
        for (int r = 0; r < TOPK_; r++) {
            int best = 0; float bv = -1e30f;
            for (int e = 0; e < E_; e++)
                if (!used[e] && gv[e] > bv) { bv = gv[e]; best = e; }
            used[best] = true; wv[r] = bv; id[r] = best; wsum += bv;
        }
        wsum = fmaxf(wsum, 1.1920929e-07f);
        for (int r = 0; r < TOPK_; r++) {
            w8[tt * TOPK_ + r] = wv[r] / wsum;
            idx8[tt * TOPK_ + r] = id[r];
        }
    }
}

// ---------------- routing ----------------
__global__ void route_kernel(const int* __restrict__ idx8, const float* __restrict__ w8,
                             int* __restrict__ etok, float* __restrict__ ew, int* __restrict__ ecnt) {
    int e = blockIdx.x, lane = threadIdx.x;
    int cnt = 0;
    for (int base = 0; base < S_ * TOPK_; base += 32) {
        int j = base + lane;
        int ee = idx8[j];
        bool match = (ee == e);
        unsigned bal = __ballot_sync(0xffffffffu, match);
        int pre = __popc(bal & ((1u << lane) - 1u));
        if (match) {
            int p = cnt + pre;
            if (p < CAP_) {
                etok[e * CAP_ + p] = j >> 3;
                ew[e * CAP_ + p] = w8[j];
            }
        }
        cnt += __popc(bal);
    }
    if (lane == 0) ecnt[e] = (cnt < CAP_) ? cnt : CAP_;
}

// ---------------- launch ----------------
extern "C" void kernel_launch(void* const* d_in, const int* in_sizes, int n_in,
                              void* d_out, int out_size) {
    (void)in_sizes; (void)n_in; (void)out_size;
    const float* hidden = (const float*)d_in[0];
    const float* cosb   = (const float*)d_in[1];
    const float* sinb   = (const float*)d_in[2];
    const float* ln1    = (const float*)d_in[3];
    const float* ln2    = (const float*)d_in[4];
    const float* Wqkv   = (const float*)d_in[5];
    const float* Wo     = (const float*)d_in[6];
    const float* qnw    = (const float*)d_in[7];
    const float* knw    = (const float*)d_in[8];
    const float* Wgu_sh = (const float*)d_in[9];
    const float* Wd_sh  = (const float*)d_in[10];
    const float* Wgate  = (const float*)d_in[11];
    const float* Wgu_e  = (const float*)d_in[12];
    const float* Wd_e   = (const float*)d_in[13];
    float* out = (float*)d_out;

    float* fb = nullptr; int* ib = nullptr;
    cudaGetSymbolAddress((void**)&fb, g_fbuf);
    cudaGetSymbolAddress((void**)&ib, g_ibuf);

    float* x      = fb + OFF_X;
    float* qkv    = fb + OFF_QKV;
    float* q      = fb + OFF_Q;
    float* k      = fb + OFF_K;
    float* v      = fb + OFF_V;
    float* attn   = fb + OFF_ATTN;
    float* h1     = fb + OFF_H1;
    float* x2     = fb + OFF_X2;
    float* actsh  = fb + OFF_ACTSH;
    float* w8     = fb + OFF_W8;
    float* expw   = fb + OFF_EXPW;
    float* actexp = fb + OFF_ACTEXP;
    int* idx8   = ib + IOFF_IDX8;
    int* exptok = ib + IOFF_EXPTOK;
    int* expcnt = ib + IOFF_EXPCNT;

    // 1. x = rmsnorm(hidden, ln1)
    rmsnorm_kernel<<<S_, 256>>>(hidden, ln1, x);
    // 2. qkv = x @ Wqkv
    mma_gemm<0><<<dim3(QKVN_ / 128, S_ / 128), 256>>>(
        x, H_, Wqkv, QKVN_, nullptr, qkv, QKVN_, H_, nullptr, nullptr, nullptr);
    // 3. RoPE + QK-norm
    qkvproc_kernel<<<S_, 256>>>(qkv, cosb, sinb, qnw, knw, q, k, v);
    // 4. attention
    attn_kernel<<<dim3(S_ / 64, NH_), 256>>>(q, k, v, attn);
    // 5. h1 = attn @ Wo + hidden
    mma_gemm<1><<<dim3(H_ / 128, S_ / 128), 256>>>(
        attn, H_, Wo, H_, hidden, h1, H_, H_, nullptr, nullptr, nullptr);
    // 6. x2 = rmsnorm(h1, ln2)
    rmsnorm_kernel<<<S_, 256>>>(h1, ln2, x2);
    // 7. shared swiglu activation
    mma_gemm<2><<<dim3(I_ / 64, S_ / 128), 256>>>(
        x2, H_, Wgu_sh, 2 * I_, nullptr, actsh, I_, H_, nullptr, nullptr, nullptr);
    // 8. out = actsh @ Wd_sh + h1
    mma_gemm<1><<<dim3(H_ / 128, S_ / 128), 256>>>(
        actsh, I_, Wd_sh, H_, h1, out, H_, I_, nullptr, nullptr, nullptr);
    // 9. gate + top-8
    gate_topk_kernel<<<S_, 64>>>(x2, Wgate, w8, idx8);
    // 10. routing
    route_kernel<<<E_, 32>>>(idx8, w8, exptok, expw, expcnt);
    // 11. expert swiglu (gather)
    mma_gemm<3><<<dim3(I_ / 64, CAP_ / 128, E_), 256>>>(
        x2, H_, Wgu_e, 2 * I_, nullptr, actexp, I_, H_, exptok, nullptr, expcnt);
    // 12. expert down + weighted scatter
    mma_gemm<4><<<dim3(H_ / 128, CAP_ / 128, E_), 256>>>(
        actexp, I_, Wd_e, H_, nullptr, out, H_, I_, exptok, expw, expcnt);
}